// round 8
// baseline (speedup 1.0000x reference)
#include <cuda_runtime.h>
#include <cuda_fp16.h>

#define NT 300000
#define NU 300000
#define ND 100000
#define EDG 2000000
#define BU 293   // ceil(NU/1024)
#define BD 98    // ceil(ND/1024)
#define GU (NU * 8 / 256)   // 9375 blocks for u-gather
#define GD (ND * 8 / 256)   // 3125 blocks for d-gather

// ---------------- scratch (static device memory; no allocations) ----------------
__device__ int g_cnt_u2t[NT];
__device__ int g_cnt_d2t[NT];
__device__ int g_cnt_t2u[NU];
__device__ int g_cnt_t2d[ND];
__device__ int g_off_t2u[NU + 1];
__device__ int g_off_t2d[ND + 1];
__device__ int g_cur_t2u[NU];
__device__ int g_cur_t2d[ND];
__device__ int g_ss_t2u[EDG];
__device__ int g_ss_t2d[EDG];
__device__ int g_part_u[BU];
__device__ int g_part_d[BD];
__device__ uint4 g_wh_t2u_h[(size_t)NT * 8];   // fp16 rows (64 halves = 8 uint4)
__device__ uint4 g_wh_t2d_h[(size_t)NT * 8];
__device__ float2 g_p_u[NU];
__device__ float2 g_p_d[ND];
__device__ float g_w1c[2][128];   // [rel][c*2+o] : W1[{0,2}] @ Wc
__device__ float g_b1c[2][2];     // [rel][o]     : b1[{0,2}] @ Wc

// ---------------- zero the degree counters ----------------
__global__ void k_zero() {
    int i = blockIdx.x * blockDim.x + threadIdx.x;
    if (i < NT) { g_cnt_u2t[i] = 0; g_cnt_d2t[i] = 0; }
    if (i < NU) g_cnt_t2u[i] = 0;
    if (i < ND) g_cnt_t2d[i] = 0;
}

// ---------------- fused degree histogram over all 4 relations ----------------
__global__ void k_hist4(const int* __restrict__ d0, const int* __restrict__ d1,
                        const int* __restrict__ d2, const int* __restrict__ d3) {
    int i = blockIdx.x * blockDim.x + threadIdx.x;
    if (i < EDG)               atomicAdd(&g_cnt_u2t[d0[i]], 1);
    else if (i < 2 * EDG)      atomicAdd(&g_cnt_d2t[d1[i - EDG]], 1);
    else if (i < 3 * EDG)      atomicAdd(&g_cnt_t2u[d2[i - 2 * EDG]], 1);
    else if (i < 4 * EDG)      atomicAdd(&g_cnt_t2d[d3[i - 3 * EDG]], 1);
}

// ---------------- block-wide inclusive scan helper (<=32 warps) ----------------
__device__ __forceinline__ int block_scan_incl(int v) {
    __shared__ int wsum[32];
    int tid = threadIdx.x, lane = tid & 31, wid = tid >> 5;
    __syncthreads();   // protect wsum reuse across calls
    int x = v;
    #pragma unroll
    for (int d = 1; d < 32; d <<= 1) {
        int t = __shfl_up_sync(0xffffffffu, x, d);
        if (lane >= d) x += t;
    }
    if (lane == 31) wsum[wid] = x;
    __syncthreads();
    if (wid == 0) {
        int nW = (blockDim.x + 31) >> 5;
        int w = (lane < nW) ? wsum[lane] : 0;
        #pragma unroll
        for (int d = 1; d < 32; d <<= 1) {
            int t = __shfl_up_sync(0xffffffffu, w, d);
            if (lane >= d) w += t;
        }
        wsum[lane] = w;
    }
    __syncthreads();
    return x + (wid > 0 ? wsum[wid - 1] : 0);
}

// ---------------- scan phase 1: per-block exclusive scan + block totals ----------------
__global__ void k_scan_part() {
    int b = blockIdx.x;
    const int* cnt; int* off; int* part; int n; int lb;
    if (b < BU) { cnt = g_cnt_t2u; off = g_off_t2u; part = g_part_u; n = NU; lb = b; }
    else        { cnt = g_cnt_t2d; off = g_off_t2d; part = g_part_d; n = ND; lb = b - BU; }
    int i = lb * 1024 + threadIdx.x;
    int v = (i < n) ? cnt[i] : 0;
    int incl = block_scan_incl(v);
    if (i < n) off[i] = incl - v;
    if (threadIdx.x == 1023) part[lb] = incl;
}

// ---------------- scan phase 2: scan the block totals (one block, both rels) ----------------
__global__ void k_scan_tot() {
    int tid = threadIdx.x;   // 512 threads
    {
        int v = (tid < BU) ? g_part_u[tid] : 0;
        int incl = block_scan_incl(v);
        if (tid < BU) g_part_u[tid] = incl - v;
        if (tid == BU - 1) g_off_t2u[NU] = incl;
    }
    {
        int v = (tid < BD) ? g_part_d[tid] : 0;
        int incl = block_scan_incl(v);
        if (tid < BD) g_part_d[tid] = incl - v;
        if (tid == BD - 1) g_off_t2d[ND] = incl;
    }
}

// ---------------- scan phase 3: add block offsets, init cursors ----------------
__global__ void k_scan_add() {
    int b = blockIdx.x;
    int* off; int* cur; const int* part; int n; int lb;
    if (b < BU) { off = g_off_t2u; cur = g_cur_t2u; part = g_part_u; n = NU; lb = b; }
    else        { off = g_off_t2d; cur = g_cur_t2d; part = g_part_d; n = ND; lb = b - BU; }
    int i = lb * 1024 + threadIdx.x;
    if (i < n) {
        int o = off[i] + part[lb];
        off[i] = o;
        cur[i] = o;
    }
}

// ---------------- CSR fill for the two live relations ----------------
__global__ void k_fill2(const int* __restrict__ s2, const int* __restrict__ d2,
                        const int* __restrict__ s3, const int* __restrict__ d3) {
    int i = blockIdx.x * blockDim.x + threadIdx.x;
    if (i < EDG) {
        int p = atomicAdd(&g_cur_t2u[d2[i]], 1);
        g_ss_t2u[p] = s2[i];
    } else {
        int e = i - EDG;
        int p = atomicAdd(&g_cur_t2d[d3[e]], 1);
        g_ss_t2d[p] = s3[e];
    }
}

// ---------------- fold classifier into layer-1 weights: W1c = W1[rel]@Wc ----------------
__global__ void k_foldw(const float* __restrict__ W1, const float* __restrict__ b1,
                        const float* __restrict__ Wc) {
    int t = threadIdx.x;             // 256 threads
    int rel = t >> 7;                // 0 -> W1[0] (u path), 1 -> W1[2] (d path)
    int idx = t & 127;
    int c = idx >> 1, o = idx & 1;
    const float* Wsrc = W1 + (rel == 0 ? 0 : 2) * 4096;
    float s = 0.f;
    #pragma unroll 8
    for (int k = 0; k < 64; k++) s += Wsrc[c * 64 + k] * Wc[k * 2 + o];
    g_w1c[rel][idx] = s;
    if (t < 4) {
        int r2 = t >> 1, o2 = t & 1;
        const float* bsrc = b1 + (r2 == 0 ? 0 : 2) * 64;
        float sb = 0.f;
        #pragma unroll 8
        for (int k = 0; k < 64; k++) sb += bsrc[k] * Wc[k * 2 + o2];
        g_b1c[r2][o2] = sb;
    }
}

// ---------------- init output with bias ----------------
__global__ void k_out_init(const float* __restrict__ bc, float* __restrict__ out) {
    int i = blockIdx.x * blockDim.x + threadIdx.x;
    if (i < 2 * NT) out[i] = __ldg(&bc[i & 1]);
}

// ------- fused dual GEMM with packed f32x2 FMA: wh_u = H@Wu+bu, wh_d = H@Wd+bd -------
__global__ __launch_bounds__(256) void k_gemm2(const float* __restrict__ H,
                                               const float* __restrict__ W0_,
                                               const float* __restrict__ b0_, int n) {
    __shared__ __align__(16) float Wu[64 * 64];
    __shared__ __align__(16) float Wd[64 * 64];
    __shared__ float As[64 * 65];
    int tid = threadIdx.x;

    const float4* Wu4 = (const float4*)(W0_ + 1 * 4096);
    const float4* Wd4 = (const float4*)(W0_ + 3 * 4096);
    float4* su = (float4*)Wu;
    float4* sd = (float4*)Wd;
    #pragma unroll
    for (int q = 0; q < 4; q++) { su[tid + q * 256] = Wu4[tid + q * 256];
                                  sd[tid + q * 256] = Wd4[tid + q * 256]; }

    int row0 = blockIdx.x * 64;
    const float4* H4 = (const float4*)H;
    #pragma unroll
    for (int q = 0; q < 4; q++) {
        int fidx = tid + q * 256;
        int r = fidx >> 4, c4 = fidx & 15;
        int gr = row0 + r;
        float4 v = make_float4(0.f, 0.f, 0.f, 0.f);
        if (gr < n) v = H4[(long)gr * 16 + c4];
        float* a = &As[r * 65 + c4 * 4];
        a[0] = v.x; a[1] = v.y; a[2] = v.z; a[3] = v.w;
    }
    __syncthreads();

    int r = tid >> 2, cg = tid & 3;
    unsigned long long au2[8], ad2[8];
    #pragma unroll
    for (int j = 0; j < 8; j++) {
        float2 t1 = make_float2(__ldg(&b0_[64 + cg * 16 + 2 * j]),
                                __ldg(&b0_[64 + cg * 16 + 2 * j + 1]));
        au2[j] = *(const unsigned long long*)&t1;
        float2 t2 = make_float2(__ldg(&b0_[192 + cg * 16 + 2 * j]),
                                __ldg(&b0_[192 + cg * 16 + 2 * j + 1]));
        ad2[j] = *(const unsigned long long*)&t2;
    }

    const float* ap = &As[r * 65];
    #pragma unroll
    for (int k = 0; k < 64; k++) {
        float a = ap[k];
        unsigned long long a2;
        asm("mov.b64 %0, {%1, %1};" : "=l"(a2) : "f"(a));
        const ulonglong2* wu = (const ulonglong2*)&Wu[k * 64 + cg * 16];
        const ulonglong2* wd = (const ulonglong2*)&Wd[k * 64 + cg * 16];
        #pragma unroll
        for (int q = 0; q < 4; q++) {
            ulonglong2 wuv = wu[q];
            ulonglong2 wdv = wd[q];
            asm("fma.rn.f32x2 %0, %1, %2, %0;" : "+l"(au2[2 * q])     : "l"(a2), "l"(wuv.x));
            asm("fma.rn.f32x2 %0, %1, %2, %0;" : "+l"(au2[2 * q + 1]) : "l"(a2), "l"(wuv.y));
            asm("fma.rn.f32x2 %0, %1, %2, %0;" : "+l"(ad2[2 * q])     : "l"(a2), "l"(wdv.x));
            asm("fma.rn.f32x2 %0, %1, %2, %0;" : "+l"(ad2[2 * q + 1]) : "l"(a2), "l"(wdv.y));
        }
    }

    int gr = row0 + r;
    if (gr < n) {
        __half2 hu[8], hd[8];
        #pragma unroll
        for (int j = 0; j < 8; j++) {
            float2 fu = *(const float2*)&au2[j];
            float2 fd = *(const float2*)&ad2[j];
            hu[j] = __floats2half2_rn(fu.x, fu.y);
            hd[j] = __floats2half2_rn(fd.x, fd.y);
        }
        uint4* ou = &g_wh_t2u_h[(long)gr * 8 + cg * 2];
        uint4* od = &g_wh_t2d_h[(long)gr * 8 + cg * 2];
        ou[0] = ((const uint4*)hu)[0];
        ou[1] = ((const uint4*)hu)[1];
        od[0] = ((const uint4*)hd)[0];
        od[1] = ((const uint4*)hd)[1];
    }
}

// ---- fused dual gather: fp16 mean-gather 64-dim -> leaky -> @W1c + b1c -> p ----
// 8 threads per node, each owning 8 half features (one uint4 = 16B); unroll-4 for MLP.
__global__ __launch_bounds__(256) void k_gather2() {
    int b = blockIdx.x;
    const uint4* wh; const int* off; const int* ss; int rel; float2* p; int t0;
    if (b < GU) { wh = g_wh_t2u_h; off = g_off_t2u; ss = g_ss_t2u; rel = 0; p = g_p_u; t0 = b * 256; }
    else        { wh = g_wh_t2d_h; off = g_off_t2d; ss = g_ss_t2d; rel = 1; p = g_p_d; t0 = (b - GU) * 256; }

    __shared__ float sw[128];
    __shared__ float sb[2];
    if (threadIdx.x < 128) sw[threadIdx.x] = g_w1c[rel][threadIdx.x];
    if (threadIdx.x < 2)   sb[threadIdx.x] = g_b1c[rel][threadIdx.x];
    __syncthreads();

    int t = t0 + threadIdx.x;
    int node = t >> 3, j = t & 7;   // grids sized exactly

    int s0 = off[node], e0 = off[node + 1];
    float acc[8];
    #pragma unroll
    for (int q = 0; q < 8; q++) acc[q] = 0.f;

    int k = s0;
    for (; k + 4 <= e0; k += 4) {
        int i0 = __ldg(&ss[k]);
        int i1 = __ldg(&ss[k + 1]);
        int i2 = __ldg(&ss[k + 2]);
        int i3 = __ldg(&ss[k + 3]);
        uint4 q0 = __ldg(&wh[(long)i0 * 8 + j]);
        uint4 q1 = __ldg(&wh[(long)i1 * 8 + j]);
        uint4 q2 = __ldg(&wh[(long)i2 * 8 + j]);
        uint4 q3 = __ldg(&wh[(long)i3 * 8 + j]);
        const uint4 qs[4] = {q0, q1, q2, q3};
        #pragma unroll
        for (int u = 0; u < 4; u++) {
            const __half2* h = (const __half2*)&qs[u];
            #pragma unroll
            for (int w = 0; w < 4; w++) {
                float2 f = __half22float2(h[w]);
                acc[w * 2 + 0] += f.x;
                acc[w * 2 + 1] += f.y;
            }
        }
    }
    if (k + 2 <= e0) {
        int i0 = __ldg(&ss[k]);
        int i1 = __ldg(&ss[k + 1]);
        uint4 q0 = __ldg(&wh[(long)i0 * 8 + j]);
        uint4 q1 = __ldg(&wh[(long)i1 * 8 + j]);
        const uint4 qs[2] = {q0, q1};
        #pragma unroll
        for (int u = 0; u < 2; u++) {
            const __half2* h = (const __half2*)&qs[u];
            #pragma unroll
            for (int w = 0; w < 4; w++) {
                float2 f = __half22float2(h[w]);
                acc[w * 2 + 0] += f.x;
                acc[w * 2 + 1] += f.y;
            }
        }
        k += 2;
    }
    if (k < e0) {
        int s = __ldg(&ss[k]);
        uint4 q = __ldg(&wh[(long)s * 8 + j]);
        const __half2* h = (const __half2*)&q;
        #pragma unroll
        for (int w = 0; w < 4; w++) {
            float2 f = __half22float2(h[w]);
            acc[w * 2 + 0] += f.x;
            acc[w * 2 + 1] += f.y;
        }
    }

    int d = e0 - s0;
    float inv = __fdividef(1.0f, (float)(d > 0 ? d : 1));
    float p0 = 0.f, p1 = 0.f;
    int c0 = j * 8;
    #pragma unroll
    for (int q = 0; q < 8; q++) {
        float m = acc[q] * inv;
        m = m > 0.f ? m : 0.01f * m;           // leaky relu
        p0 += m * sw[(c0 + q) * 2];
        p1 += m * sw[(c0 + q) * 2 + 1];
    }
    #pragma unroll
    for (int o = 4; o > 0; o >>= 1) {
        p0 += __shfl_down_sync(0xffffffffu, p0, o, 8);
        p1 += __shfl_down_sync(0xffffffffu, p1, o, 8);
    }
    if (j == 0) p[node] = make_float2(p0 + sb[0], p1 + sb[1]);
}

// -------- final: edge-parallel scatter of mean contributions (red.v2.f32) --------
__global__ void k_scatter(const int* __restrict__ su, const int* __restrict__ du,
                          const int* __restrict__ sd, const int* __restrict__ dd,
                          float* __restrict__ out) {
    int i = blockIdx.x * blockDim.x + threadIdx.x;
    int s, d; float2 v; int c;
    if (i < EDG) {
        s = __ldg(&su[i]); d = __ldg(&du[i]);
        v = g_p_u[s];
        c = g_cnt_u2t[d];
    } else {
        int e = i - EDG;
        s = __ldg(&sd[e]); d = __ldg(&dd[e]);
        v = g_p_d[s];
        c = g_cnt_d2t[d];
    }
    float inv = __fdividef(1.0f, (float)c);
    float x = v.x * inv, y = v.y * inv;
    asm volatile("red.global.add.v2.f32 [%0], {%1, %2};"
                 :: "l"(out + 2 * (size_t)d), "f"(x), "f"(y) : "memory");
}

extern "C" void kernel_launch(void* const* d_in, const int* in_sizes, int n_in,
                              void* d_out, int out_size) {
    const float* features = (const float*)d_in[0];
    const float* W0 = (const float*)d_in[3];
    const float* b0 = (const float*)d_in[4];
    const float* W1 = (const float*)d_in[5];
    const float* b1 = (const float*)d_in[6];
    const float* Wc = (const float*)d_in[7];
    const float* bc = (const float*)d_in[8];
    const int* src_u2t = (const int*)d_in[9];
    const int* dst_u2t = (const int*)d_in[10];
    const int* src_t2u = (const int*)d_in[11];
    const int* dst_t2u = (const int*)d_in[12];
    const int* src_d2t = (const int*)d_in[13];
    const int* dst_d2t = (const int*)d_in[14];
    const int* src_t2d = (const int*)d_in[15];
    const int* dst_t2d = (const int*)d_in[16];
    float* out = (float*)d_out;

    const int TPB = 256;

    // Side stream + events, created once and reused across invocations
    // (host-side resource creation is legal; reuse avoids accumulating handles).
    static cudaStream_t s1 = nullptr;
    static cudaEvent_t e0 = nullptr, e1 = nullptr;
    if (!s1) {
        cudaStreamCreateWithFlags(&s1, cudaStreamNonBlocking);
        cudaEventCreateWithFlags(&e0, cudaEventDisableTiming);
        cudaEventCreateWithFlags(&e1, cudaEventDisableTiming);
    }

    cudaEventRecord(e0, 0);
    cudaStreamWaitEvent(s1, e0, 0);

    // ---- side stream: input-only work (GEMM, weight folding, output init) ----
    k_gemm2<<<(NT + 63) / 64, TPB, 0, s1>>>(features, W0, b0, NT);
    k_foldw<<<1, 256, 0, s1>>>(W1, b1, Wc);
    k_out_init<<<(2 * NT + TPB - 1) / TPB, TPB, 0, s1>>>(bc, out);
    cudaEventRecord(e1, s1);

    // ---- main stream: CSR build chain ----
    k_zero<<<(NT + TPB - 1) / TPB, TPB>>>();
    k_hist4<<<(4 * EDG) / TPB, TPB>>>(dst_u2t, dst_d2t, dst_t2u, dst_t2d);
    k_scan_part<<<BU + BD, 1024>>>();
    k_scan_tot<<<1, 512>>>();
    k_scan_add<<<BU + BD, 1024>>>();
    k_fill2<<<(2 * EDG) / TPB, TPB>>>(src_t2u, dst_t2u, src_t2d, dst_t2d);

    // join side stream, then gather + scatter
    cudaStreamWaitEvent(0, e1, 0);
    k_gather2<<<GU + GD, TPB>>>();
    k_scatter<<<(2 * EDG) / TPB, TPB>>>(src_u2t, dst_u2t, src_d2t, dst_d2t, out);
}